// round 1
// baseline (speedup 1.0000x reference)
#include <cuda_runtime.h>
#include <math.h>

// ---- problem constants ----
#define BB 8
#define NTOK 1024
#define TT 1026            // N + cls + dict
#define DD 256
#define HH 8
#define LL 6
#define HD3 6144           // H*D*3
#define OD 2048            // H*D
#define ED 1024            // EXP*D
#define MM (BB*TT)         // 8208 rows
#define BHn (BB*HH)        // 64
#define TS 1040            // padded score row stride (16B-aligned float4)

// ---- scratch (device globals; no allocs allowed) ----
__device__ float g_h [(size_t)MM*DD];
__device__ float g_ln[(size_t)MM*DD];
__device__ float g_q [(size_t)BHn*TT*DD];
__device__ float g_k [(size_t)BHn*TT*DD];
__device__ float g_v [(size_t)BHn*TT*DD];
__device__ float g_s [(size_t)BHn*TT*TS];
__device__ float g_o [(size_t)MM*OD];
__device__ float g_m [(size_t)MM*ED];

__device__ __forceinline__ float gelu_exact(float x) {
    return 0.5f * x * (1.0f + erff(x * 0.70710678118654752440f));
}

// ---- embed: h = concat(x, cls, dict) ----
__global__ void init_h_kernel(const float* __restrict__ x,
                              const float* __restrict__ cls,
                              const float* __restrict__ dict) {
    long i = (long)blockIdx.x * blockDim.x + threadIdx.x;
    if (i >= (long)MM * DD) return;
    int d = (int)(i % DD);
    long r = i / DD;
    int t = (int)(r % TT);
    int b = (int)(r / TT);
    float v;
    if (t < NTOK)        v = x[((long)b * NTOK + t) * DD + d];
    else if (t == NTOK)  v = cls[d];
    else                 v = dict[d];
    g_h[i] = v;
}

// ---- layernorm: one block (256 thr) per row of 256 ----
__global__ void ln_kernel(const float* __restrict__ in, float* __restrict__ out,
                          const float* __restrict__ gamma, const float* __restrict__ beta) {
    int row = blockIdx.x;
    int tid = threadIdx.x;
    float x = in[(long)row * DD + tid];
    float s = x, s2 = x * x;
    #pragma unroll
    for (int o = 16; o > 0; o >>= 1) {
        s  += __shfl_xor_sync(0xFFFFFFFFu, s,  o);
        s2 += __shfl_xor_sync(0xFFFFFFFFu, s2, o);
    }
    __shared__ float sh[8], sh2[8];
    int w = tid >> 5;
    if ((tid & 31) == 0) { sh[w] = s; sh2[w] = s2; }
    __syncthreads();
    if (tid < 32) {
        float a  = (tid < 8) ? sh[tid]  : 0.f;
        float a2 = (tid < 8) ? sh2[tid] : 0.f;
        #pragma unroll
        for (int o = 4; o > 0; o >>= 1) {
            a  += __shfl_xor_sync(0xFFFFFFFFu, a,  o);
            a2 += __shfl_xor_sync(0xFFFFFFFFu, a2, o);
        }
        if (tid == 0) { sh[0] = a; sh2[0] = a2; }
    }
    __syncthreads();
    float mean = sh[0] * (1.0f / DD);
    float var  = sh2[0] * (1.0f / DD) - mean * mean;
    float r = rsqrtf(var + 1e-5f);
    out[(long)row * DD + tid] = (x - mean) * r * gamma[tid] + beta[tid];
}

// ---- softmax over score rows (length TT, stride TS) ----
__global__ void softmax_kernel() {
    long row = blockIdx.x;             // bh*TT + t
    int bh = (int)(row / TT);
    int t  = (int)(row % TT);
    float* p = g_s + (size_t)bh * TT * TS + (size_t)t * TS;
    int tid = threadIdx.x;
    float v[5];
    float mx = -1e30f;
    #pragma unroll
    for (int it = 0; it < 5; it++) {
        int j = tid + it * 256;
        if (j < TT) { v[it] = p[j]; mx = fmaxf(mx, v[it]); }
    }
    __shared__ float red_m[8], red_s[8];
    #pragma unroll
    for (int o = 16; o > 0; o >>= 1) mx = fmaxf(mx, __shfl_xor_sync(0xFFFFFFFFu, mx, o));
    if ((tid & 31) == 0) red_m[tid >> 5] = mx;
    __syncthreads();
    if (tid < 32) {
        float a = (tid < 8) ? red_m[tid] : -1e30f;
        #pragma unroll
        for (int o = 4; o > 0; o >>= 1) a = fmaxf(a, __shfl_xor_sync(0xFFFFFFFFu, a, o));
        if (tid == 0) red_m[0] = a;
    }
    __syncthreads();
    mx = red_m[0];
    float sum = 0.f;
    #pragma unroll
    for (int it = 0; it < 5; it++) {
        int j = tid + it * 256;
        if (j < TT) { v[it] = __expf(v[it] - mx); sum += v[it]; }
    }
    #pragma unroll
    for (int o = 16; o > 0; o >>= 1) sum += __shfl_xor_sync(0xFFFFFFFFu, sum, o);
    if ((tid & 31) == 0) red_s[tid >> 5] = sum;
    __syncthreads();
    if (tid < 32) {
        float a = (tid < 8) ? red_s[tid] : 0.f;
        #pragma unroll
        for (int o = 4; o > 0; o >>= 1) a += __shfl_xor_sync(0xFFFFFFFFu, a, o);
        if (tid == 0) red_s[0] = a;
    }
    __syncthreads();
    float inv = 1.0f / red_s[0];
    #pragma unroll
    for (int it = 0; it < 5; it++) {
        int j = tid + it * 256;
        if (j < TT) p[j] = v[it] * inv;
    }
}

// ---- generic fp32 SGEMM: 128x128x8 tiles, 256 threads, 8x8 microtile ----
// A [M,K] row-major. B: TB? [N,K] : [K,N] row-major. C row-major ldc.
// EPI: 0 = (bias?) store, 1 = bias+gelu store, 2 = qkv scatter to g_q/g_k/g_v
// COFF: 0 = C += z*sC ; 1 = attention-O layout C += (z/H)*(T*OD) + (z%H)*DD
template<bool TB, int EPI, int COFF>
__global__ __launch_bounds__(256)
void gemm128(const float* __restrict__ A, int lda, long sA,
             const float* __restrict__ Bm, int ldb, long sB,
             const float* __restrict__ bias,
             float* __restrict__ C, int ldc, long sC,
             int M, int N, int K)
{
    constexpr int BM = 128, BN = 128, BK = 8;
    __shared__ float As[BK][BM];
    __shared__ float Bs[BK][BN];

    int z = blockIdx.z;
    A  += (size_t)z * sA;
    Bm += (size_t)z * sB;
    if (COFF == 0) C += (size_t)z * sC;
    else           C += (size_t)(z / HH) * ((size_t)TT * OD) + (size_t)(z % HH) * DD;

    int bm = blockIdx.y * BM, bn = blockIdx.x * BN;
    int tid = threadIdx.x;
    int tx = tid & 15, ty = tid >> 4;

    float acc[8][8];
    #pragma unroll
    for (int i = 0; i < 8; i++)
        #pragma unroll
        for (int j = 0; j < 8; j++) acc[i][j] = 0.f;

    int a_row = tid >> 1;
    int a_k   = (tid & 1) * 4;

    for (int k0 = 0; k0 < K; k0 += BK) {
        // load A tile (transposed into As[k][m])
        {
            float4 v = make_float4(0.f, 0.f, 0.f, 0.f);
            int gm = bm + a_row;
            if (gm < M) {
                int gk = k0 + a_k;
                if (gk + 3 < K) {
                    v = *(const float4*)(A + (size_t)gm * lda + gk);
                } else {
                    float t0 = (gk + 0 < K) ? A[(size_t)gm * lda + gk + 0] : 0.f;
                    float t1 = (gk + 1 < K) ? A[(size_t)gm * lda + gk + 1] : 0.f;
                    float t2 = (gk + 2 < K) ? A[(size_t)gm * lda + gk + 2] : 0.f;
                    float t3 = (gk + 3 < K) ? A[(size_t)gm * lda + gk + 3] : 0.f;
                    v = make_float4(t0, t1, t2, t3);
                }
            }
            As[a_k + 0][a_row] = v.x; As[a_k + 1][a_row] = v.y;
            As[a_k + 2][a_row] = v.z; As[a_k + 3][a_row] = v.w;
        }
        // load B tile
        if (!TB) {
            int bk  = tid >> 5;          // 0..7
            int bn4 = (tid & 31) * 4;    // 0..124
            float4 v = make_float4(0.f, 0.f, 0.f, 0.f);
            int gk = k0 + bk;
            int gn = bn + bn4;
            if (gk < K && gn < N) {
                if (gn + 3 < N) {
                    v = *(const float4*)(Bm + (size_t)gk * ldb + gn);
                } else {
                    float t0 = Bm[(size_t)gk * ldb + gn];
                    float t1 = (gn + 1 < N) ? Bm[(size_t)gk * ldb + gn + 1] : 0.f;
                    float t2 = (gn + 2 < N) ? Bm[(size_t)gk * ldb + gn + 2] : 0.f;
                    float t3 = (gn + 3 < N) ? Bm[(size_t)gk * ldb + gn + 3] : 0.f;
                    v = make_float4(t0, t1, t2, t3);
                }
            }
            Bs[bk][bn4 + 0] = v.x; Bs[bk][bn4 + 1] = v.y;
            Bs[bk][bn4 + 2] = v.z; Bs[bk][bn4 + 3] = v.w;
        } else {
            int b_n = tid >> 1;
            int b_k = (tid & 1) * 4;
            float4 v = make_float4(0.f, 0.f, 0.f, 0.f);
            int gn = bn + b_n;
            if (gn < N) {
                int gk = k0 + b_k;
                if (gk + 3 < K) {
                    v = *(const float4*)(Bm + (size_t)gn * ldb + gk);
                } else {
                    float t0 = (gk + 0 < K) ? Bm[(size_t)gn * ldb + gk + 0] : 0.f;
                    float t1 = (gk + 1 < K) ? Bm[(size_t)gn * ldb + gk + 1] : 0.f;
                    float t2 = (gk + 2 < K) ? Bm[(size_t)gn * ldb + gk + 2] : 0.f;
                    float t3 = (gk + 3 < K) ? Bm[(size_t)gn * ldb + gk + 3] : 0.f;
                    v = make_float4(t0, t1, t2, t3);
                }
            }
            Bs[b_k + 0][b_n] = v.x; Bs[b_k + 1][b_n] = v.y;
            Bs[b_k + 2][b_n] = v.z; Bs[b_k + 3][b_n] = v.w;
        }
        __syncthreads();

        #pragma unroll
        for (int k = 0; k < BK; k++) {
            float af[8], bf[8];
            #pragma unroll
            for (int i = 0; i < 8; i++) af[i] = As[k][ty * 8 + i];
            #pragma unroll
            for (int j = 0; j < 8; j++) bf[j] = Bs[k][tx * 8 + j];
            #pragma unroll
            for (int i = 0; i < 8; i++)
                #pragma unroll
                for (int j = 0; j < 8; j++)
                    acc[i][j] = fmaf(af[i], bf[j], acc[i][j]);
        }
        __syncthreads();
    }

    // epilogue
    #pragma unroll
    for (int i = 0; i < 8; i++) {
        int gm = bm + ty * 8 + i;
        if (gm >= M) continue;
        #pragma unroll
        for (int j = 0; j < 8; j++) {
            int gn = bn + tx * 8 + j;
            if (gn >= N) continue;
            float v = acc[i][j];
            if (bias) v += bias[gn];
            if (EPI == 1) v = gelu_exact(v);
            if (EPI == 2) {
                int head = gn / (DD * 3);
                int rem  = gn % (DD * 3);
                int f = rem / 3, c = rem % 3;
                int b = gm / TT, t = gm % TT;
                size_t o = ((size_t)(b * HH + head) * TT + t) * DD + f;
                if (c == 0)      g_q[o] = v * 0.0625f;   // 1/sqrt(256)
                else if (c == 1) g_k[o] = v * 0.0625f;
                else             g_v[o] = v;
            } else {
                C[(size_t)gm * ldc + gn] = v;
            }
        }
    }
}

// ---- final output: split h into (x_out, cls_out, dict_out) ----
__global__ void out_kernel(float* __restrict__ out) {
    long i = (long)blockIdx.x * blockDim.x + threadIdx.x;
    if (i >= (long)MM * DD) return;
    int d = (int)(i % DD);
    long r = i / DD;
    int t = (int)(r % TT);
    int b = (int)(r / TT);
    float v = g_h[i];
    if (t < NTOK)        out[((long)b * NTOK + t) * DD + d] = v;
    else if (t == NTOK)  out[(long)BB * NTOK * DD + (long)b * DD + d] = v;
    else                 out[(long)BB * NTOK * DD + (long)BB * DD + (long)b * DD + d] = v;
}

extern "C" void kernel_launch(void* const* d_in, const int* in_sizes, int n_in,
                              void* d_out, int out_size) {
    const float* x      = (const float*)d_in[0];
    const float* cls    = (const float*)d_in[1];
    const float* dict   = (const float*)d_in[2];
    const float* ln1_g  = (const float*)d_in[3];
    const float* ln1_b  = (const float*)d_in[4];
    const float* qkv_w  = (const float*)d_in[5];
    const float* qkv_b  = (const float*)d_in[6];
    const float* proj_w = (const float*)d_in[7];
    const float* proj_b = (const float*)d_in[8];
    const float* ln2_g  = (const float*)d_in[9];
    const float* ln2_b  = (const float*)d_in[10];
    const float* mlp_w1 = (const float*)d_in[11];
    const float* mlp_b1 = (const float*)d_in[12];
    const float* mlp_w2 = (const float*)d_in[13];
    const float* mlp_b2 = (const float*)d_in[14];

    float *gh, *gln, *gq, *gk, *gv, *gs, *go, *gm;
    cudaGetSymbolAddress((void**)&gh,  g_h);
    cudaGetSymbolAddress((void**)&gln, g_ln);
    cudaGetSymbolAddress((void**)&gq,  g_q);
    cudaGetSymbolAddress((void**)&gk,  g_k);
    cudaGetSymbolAddress((void**)&gv,  g_v);
    cudaGetSymbolAddress((void**)&gs,  g_s);
    cudaGetSymbolAddress((void**)&go,  g_o);
    cudaGetSymbolAddress((void**)&gm,  g_m);

    long total = (long)MM * DD;
    init_h_kernel<<<(unsigned)((total + 255) / 256), 256>>>(x, cls, dict);

    for (int l = 0; l < LL; l++) {
        // LN1
        ln_kernel<<<MM, 256>>>(gh, gln, ln1_g + (size_t)l * DD, ln1_b + (size_t)l * DD);

        // QKV gemm + scatter  (M=8208, N=6144, K=256)
        {
            dim3 g(HD3 / 128, (MM + 127) / 128, 1);
            gemm128<false, 2, 0><<<g, 256>>>(
                gln, DD, 0,
                qkv_w + (size_t)l * DD * HD3, HD3, 0,
                qkv_b + (size_t)l * HD3,
                gh /*unused*/, DD, 0,
                MM, HD3, DD);
        }

        // scores = Q @ K^T (batched over 64 heads)
        {
            dim3 g((TT + 127) / 128, (TT + 127) / 128, BHn);
            gemm128<true, 0, 0><<<g, 256>>>(
                gq, DD, (long)TT * DD,
                gk, DD, (long)TT * DD,
                nullptr,
                gs, TS, (long)TT * TS,
                TT, TT, DD);
        }

        softmax_kernel<<<BHn * TT, 256>>>();

        // O = W @ V, written into [B,T,H*D] layout
        {
            dim3 g((DD + 127) / 128, (TT + 127) / 128, BHn);
            gemm128<false, 0, 1><<<g, 256>>>(
                gs, TS, (long)TT * TS,
                gv, DD, (long)TT * DD,
                nullptr,
                go, OD, 0,
                TT, DD, TT);
        }

        // proj: [8208,2048] @ [2048,256] -> gh
        {
            dim3 g((DD + 127) / 128, (MM + 127) / 128, 1);
            gemm128<false, 0, 0><<<g, 256>>>(
                go, OD, 0,
                proj_w + (size_t)l * OD * DD, DD, 0,
                proj_b + (size_t)l * DD,
                gh, DD, 0,
                MM, DD, OD);
        }

        // LN2
        ln_kernel<<<MM, 256>>>(gh, gln, ln2_g + (size_t)l * DD, ln2_b + (size_t)l * DD);

        // MLP1 + gelu: [8208,256] @ [256,1024]
        {
            dim3 g(ED / 128, (MM + 127) / 128, 1);
            gemm128<false, 1, 0><<<g, 256>>>(
                gln, DD, 0,
                mlp_w1 + (size_t)l * DD * ED, ED, 0,
                mlp_b1 + (size_t)l * ED,
                gm, ED, 0,
                MM, ED, DD);
        }

        // MLP2 + gelu: [8208,1024] @ [1024,256] -> gh (next layer input)
        {
            dim3 g(DD / 128, (MM + 127) / 128, 1);
            gemm128<false, 1, 0><<<g, 256>>>(
                gm, ED, 0,
                mlp_w2 + (size_t)l * ED * DD, DD, 0,
                mlp_b2 + (size_t)l * DD,
                gh, DD, 0,
                MM, DD, ED);
        }
    }

    out_kernel<<<(unsigned)((total + 255) / 256), 256>>>((float*)d_out);
}

// round 3
// speedup vs baseline: 2.0212x; 2.0212x over previous
#include <cuda_runtime.h>
#include <cuda_bf16.h>
#include <math.h>
#include <stdint.h>

// ---- problem constants ----
#define BB 8
#define NTOK 1024
#define TT 1026            // N + cls + dict
#define DD 256
#define HH 8
#define LL 6
#define HD3 6144           // H*D*3
#define OD 2048            // H*D
#define ED 1024            // EXP*D
#define MM (BB*TT)         // 8208 rows
#define BHn (BB*HH)        // 64
#define TS 1040            // padded fp32 score row stride
#define WK 1152            // padded K (mult of 128) for prob/vT operands

typedef __nv_bfloat16 bf16;

// ---- scratch (device globals; no allocs allowed) ----
__device__ __align__(16) float g_h [(size_t)MM*DD];
__device__ __align__(16) float g_s [(size_t)BHn*TT*TS];
__device__ __align__(16) bf16 g_lnh[(size_t)MM*DD];
__device__ __align__(16) bf16 g_lnl[(size_t)MM*DD];
__device__ __align__(16) bf16 g_qh[(size_t)BHn*TT*DD];
__device__ __align__(16) bf16 g_ql[(size_t)BHn*TT*DD];
__device__ __align__(16) bf16 g_kh[(size_t)BHn*TT*DD];
__device__ __align__(16) bf16 g_kl[(size_t)BHn*TT*DD];
__device__ __align__(16) bf16 g_vTh[(size_t)BHn*DD*WK];
__device__ __align__(16) bf16 g_vTl[(size_t)BHn*DD*WK];
__device__ __align__(16) bf16 g_wph[(size_t)BHn*TT*WK];
__device__ __align__(16) bf16 g_wpl[(size_t)BHn*TT*WK];
__device__ __align__(16) bf16 g_oh[(size_t)MM*OD];
__device__ __align__(16) bf16 g_ol[(size_t)MM*OD];
__device__ __align__(16) bf16 g_mh[(size_t)MM*ED];
__device__ __align__(16) bf16 g_ml[(size_t)MM*ED];
// transposed + split weights [N,K] per layer
__device__ __align__(16) bf16 g_qkvTh[(size_t)LL*HD3*DD];
__device__ __align__(16) bf16 g_qkvTl[(size_t)LL*HD3*DD];
__device__ __align__(16) bf16 g_projTh[(size_t)LL*DD*OD];
__device__ __align__(16) bf16 g_projTl[(size_t)LL*DD*OD];
__device__ __align__(16) bf16 g_w1Th[(size_t)LL*ED*DD];
__device__ __align__(16) bf16 g_w1Tl[(size_t)LL*ED*DD];
__device__ __align__(16) bf16 g_w2Th[(size_t)LL*DD*ED];
__device__ __align__(16) bf16 g_w2Tl[(size_t)LL*DD*ED];

__device__ __forceinline__ float gelu_exact(float x) {
    return 0.5f * x * (1.0f + erff(x * 0.70710678118654752440f));
}

__device__ __forceinline__ uint32_t smem_u32(const void* p) {
    uint32_t a;
    asm("{ .reg .u64 t; cvta.to.shared.u64 t, %1; cvt.u32.u64 %0, t; }" : "=r"(a) : "l"(p));
    return a;
}

__device__ __forceinline__ void ldsm4(uint32_t* r, uint32_t addr) {
    asm volatile("ldmatrix.sync.aligned.m8n8.x4.shared.b16 {%0,%1,%2,%3}, [%4];"
                 : "=r"(r[0]), "=r"(r[1]), "=r"(r[2]), "=r"(r[3]) : "r"(addr));
}

__device__ __forceinline__ void mma16816(float* d, const uint32_t* a, const uint32_t* b) {
    asm volatile(
        "mma.sync.aligned.m16n8k16.row.col.f32.bf16.bf16.f32 "
        "{%0,%1,%2,%3}, {%4,%5,%6,%7}, {%8,%9}, {%0,%1,%2,%3};"
        : "+f"(d[0]), "+f"(d[1]), "+f"(d[2]), "+f"(d[3])
        : "r"(a[0]), "r"(a[1]), "r"(a[2]), "r"(a[3]), "r"(b[0]), "r"(b[1]));
}

__device__ __forceinline__ void split_store(bf16* dh, bf16* dl, size_t off, float v) {
    bf16 h = __float2bfloat16(v);
    dh[off] = h;
    dl[off] = __float2bfloat16(v - __bfloat162float(h));
}

// per-element epilogue
template<int EPI>
__device__ __forceinline__ void epi_store(int gm, int gn, float v, int M, int N,
                                          const float* __restrict__ bias,
                                          float* __restrict__ C, int ldc, long sC, int z) {
    if (gm >= M || gn >= N) return;
    if constexpr (EPI == 0) {                 // scores -> fp32
        C[(size_t)z * sC + (size_t)gm * ldc + gn] = v;
    } else if constexpr (EPI == 1) {          // qkv scatter
        v += bias[gn];
        int head = gn / (DD * 3);
        int rem = gn - head * (DD * 3);
        int f = rem / 3, cc = rem - f * 3;
        int b = gm / TT, t = gm - b * TT;
        int bh = b * HH + head;
        if (cc == 2) {
            split_store(g_vTh, g_vTl, ((size_t)bh * DD + f) * WK + t, v);
        } else {
            v *= 0.0625f;                     // 1/sqrt(256)
            size_t o = ((size_t)bh * TT + t) * DD + f;
            if (cc == 0) split_store(g_qh, g_ql, o, v);
            else         split_store(g_kh, g_kl, o, v);
        }
    } else if constexpr (EPI == 2) {          // WV -> o split
        int b = z >> 3, head = z & 7;
        split_store(g_oh, g_ol, ((size_t)b * TT + gm) * OD + (size_t)head * DD + gn, v);
    } else if constexpr (EPI == 3) {          // proj -> fp32 + bias
        C[(size_t)gm * ldc + gn] = v + bias[gn];
    } else if constexpr (EPI == 4) {          // mlp1: bias+gelu -> m split
        split_store(g_mh, g_ml, (size_t)gm * ED + gn, gelu_exact(v + bias[gn]));
    } else {                                  // mlp2: bias+gelu -> fp32
        C[(size_t)gm * ldc + gn] = gelu_exact(v + bias[gn]);
    }
}

// ============ HMMA bf16x3 GEMM: 128x128 block, BK=32, 256 threads ============
// A: [M,K] K-major (hi/lo). B: [N,K] K-major (hi/lo). D = A @ B^T.
// Warp grid 4(m) x 2(n); warp tile 32x64; mma.sync m16n8k16.
#define SLD 40  // padded smem row stride in bf16 (80 bytes)

template<int EPI>
__global__ void __launch_bounds__(256, 1) mma_gemm(
    const bf16* __restrict__ Ah, const bf16* __restrict__ Al, int lda, long sA,
    const bf16* __restrict__ Bh, const bf16* __restrict__ Bl, int ldb, long sB,
    const float* __restrict__ bias,
    float* __restrict__ C, int ldc, long sC,
    int M, int N, int K)
{
    __shared__ bf16 As_h[128 * SLD], As_l[128 * SLD];
    __shared__ bf16 Bs_h[128 * SLD], Bs_l[128 * SLD];

    int tid = threadIdx.x, lane = tid & 31, wid = tid >> 5;
    int wm = wid >> 1, wn = wid & 1;
    int z = blockIdx.z;
    Ah += (size_t)z * sA;  Al += (size_t)z * sA;
    Bh += (size_t)z * sB;  Bl += (size_t)z * sB;
    int bm = blockIdx.y * 128, bn = blockIdx.x * 128;

    // global-load coordinates (2 vectors of 8 bf16 per operand per thread)
    int row0 = tid >> 2,        cv0 = (tid & 3) * 8;
    int row1 = (tid + 256) >> 2, cv1 = (tid & 3) * 8;  // rows 64..127
    bool aval0 = (bm + row0) < M, aval1 = (bm + row1) < M;
    bool bval0 = (bn + row0) < N, bval1 = (bn + row1) < N;
    const bf16* pAh0 = Ah + (size_t)(bm + row0) * lda + cv0;
    const bf16* pAh1 = Ah + (size_t)(bm + row1) * lda + cv1;
    const bf16* pAl0 = Al + (size_t)(bm + row0) * lda + cv0;
    const bf16* pAl1 = Al + (size_t)(bm + row1) * lda + cv1;
    const bf16* pBh0 = Bh + (size_t)(bn + row0) * ldb + cv0;
    const bf16* pBh1 = Bh + (size_t)(bn + row1) * ldb + cv1;
    const bf16* pBl0 = Bl + (size_t)(bn + row0) * ldb + cv0;
    const bf16* pBl1 = Bl + (size_t)(bn + row1) * ldb + cv1;
    uint32_t s_off0 = (uint32_t)(row0 * SLD + cv0) * 2;
    uint32_t s_off1 = (uint32_t)(row1 * SLD + cv1) * 2;

    uint32_t as_h = smem_u32(As_h), as_l = smem_u32(As_l);
    uint32_t bs_h = smem_u32(Bs_h), bs_l = smem_u32(Bs_l);

    float d[2][8][4];
    #pragma unroll
    for (int i = 0; i < 2; i++)
        #pragma unroll
        for (int j = 0; j < 8; j++)
            #pragma unroll
            for (int q = 0; q < 4; q++) d[i][j][q] = 0.f;

    // ldmatrix lane addressing
    int group = lane >> 3, lrow = lane & 7;
    int a_row = wm * 32 + (group & 1) * 8 + lrow;   // + mt*16
    int a_ko  = (group >> 1) * 8;                   // + ks
    int b_row = wn * 64 + (group >> 1) * 8 + lrow;  // + np*16
    int b_ko  = (group & 1) * 8;

    const uint4 Z4 = make_uint4(0u, 0u, 0u, 0u);
    uint4 rAh0, rAh1, rAl0, rAl1, rBh0, rBh1, rBl0, rBl1;

    int nit = K >> 5;
    // prologue load
    rAh0 = aval0 ? *(const uint4*)pAh0 : Z4;  rAh1 = aval1 ? *(const uint4*)pAh1 : Z4;
    rAl0 = aval0 ? *(const uint4*)pAl0 : Z4;  rAl1 = aval1 ? *(const uint4*)pAl1 : Z4;
    rBh0 = bval0 ? *(const uint4*)pBh0 : Z4;  rBh1 = bval1 ? *(const uint4*)pBh1 : Z4;
    rBl0 = bval0 ? *(const uint4*)pBl0 : Z4;  rBl1 = bval1 ? *(const uint4*)pBl1 : Z4;

    for (int c = 0; c < nit; c++) {
        // store staged tile to smem
        *(uint4*)((char*)As_h + s_off0) = rAh0;  *(uint4*)((char*)As_h + s_off1) = rAh1;
        *(uint4*)((char*)As_l + s_off0) = rAl0;  *(uint4*)((char*)As_l + s_off1) = rAl1;
        *(uint4*)((char*)Bs_h + s_off0) = rBh0;  *(uint4*)((char*)Bs_h + s_off1) = rBh1;
        *(uint4*)((char*)Bs_l + s_off0) = rBl0;  *(uint4*)((char*)Bs_l + s_off1) = rBl1;
        __syncthreads();

        // prefetch next tile (overlaps with mma below)
        if (c + 1 < nit) {
            int adv = (c + 1) * 32;
            rAh0 = aval0 ? *(const uint4*)(pAh0 + adv) : Z4;
            rAh1 = aval1 ? *(const uint4*)(pAh1 + adv) : Z4;
            rAl0 = aval0 ? *(const uint4*)(pAl0 + adv) : Z4;
            rAl1 = aval1 ? *(const uint4*)(pAl1 + adv) : Z4;
            rBh0 = bval0 ? *(const uint4*)(pBh0 + adv) : Z4;
            rBh1 = bval1 ? *(const uint4*)(pBh1 + adv) : Z4;
            rBl0 = bval0 ? *(const uint4*)(pBl0 + adv) : Z4;
            rBl1 = bval1 ? *(const uint4*)(pBl1 + adv) : Z4;
        }

        #pragma unroll
        for (int ks = 0; ks < 32; ks += 16) {
            uint32_t a_hf[2][4], a_lf[2][4], b_hf[4][4], b_lf[4][4];
            #pragma unroll
            for (int mt = 0; mt < 2; mt++) {
                uint32_t off = (uint32_t)((a_row + mt * 16) * SLD + ks + a_ko) * 2;
                ldsm4(a_hf[mt], as_h + off);
                ldsm4(a_lf[mt], as_l + off);
            }
            #pragma unroll
            for (int np = 0; np < 4; np++) {
                uint32_t off = (uint32_t)((b_row + np * 16) * SLD + ks + b_ko) * 2;
                ldsm4(b_hf[np], bs_h + off);
                ldsm4(b_lf[np], bs_l + off);
            }
            #pragma unroll
            for (int mt = 0; mt < 2; mt++)
                #pragma unroll
                for (int np = 0; np < 4; np++)
                    #pragma unroll
                    for (int hq = 0; hq < 2; hq++) {
                        float* acc = d[mt][np * 2 + hq];
                        mma16816(acc, a_hf[mt], &b_hf[np][hq * 2]);
                        mma16816(acc, a_lf[mt], &b_hf[np][hq * 2]);
                        mma16816(acc, a_hf[mt], &b_lf[np][hq * 2]);
                    }
        }
        __syncthreads();
    }

    // epilogue
    #pragma unroll
    for (int mt = 0; mt < 2; mt++)
        #pragma unroll
        for (int nt = 0; nt < 8; nt++) {
            int r0 = bm + wm * 32 + mt * 16 + (lane >> 2);
            int c0 = bn + wn * 64 + nt * 8 + (lane & 3) * 2;
            float* dd = d[mt][nt];
            epi_store<EPI>(r0,     c0,     dd[0], M, N, bias, C, ldc, sC, z);
            epi_store<EPI>(r0,     c0 + 1, dd[1], M, N, bias, C, ldc, sC, z);
            epi_store<EPI>(r0 + 8, c0,     dd[2], M, N, bias, C, ldc, sC, z);
            epi_store<EPI>(r0 + 8, c0 + 1, dd[3], M, N, bias, C, ldc, sC, z);
        }
}

// ---- transpose + split weights: src [K,N] fp32 -> dh/dl [N,K] bf16 ----
__global__ void tsplit(const float* __restrict__ src, bf16* __restrict__ dh,
                       bf16* __restrict__ dl, int K, int N) {
    __shared__ float t[32][33];
    int n0 = blockIdx.x * 32, k0 = blockIdx.y * 32;
    int tx = threadIdx.x, ty = threadIdx.y;  // 32 x 8
    #pragma unroll
    for (int i = 0; i < 4; i++) {
        int k = k0 + ty + i * 8, n = n0 + tx;
        if (k < K && n < N) t[ty + i * 8][tx] = src[(size_t)k * N + n];
    }
    __syncthreads();
    #pragma unroll
    for (int i = 0; i < 4; i++) {
        int n = n0 + ty + i * 8, k = k0 + tx;
        if (n < N && k < K) {
            float v = t[tx][ty + i * 8];
            split_store(dh, dl, (size_t)n * K + k, v);
        }
    }
}

// ---- zero the K-pads of prob/vT buffers (cols [TT,WK)) ----
__global__ void zero_pads() {
    long i = (long)blockIdx.x * blockDim.x + threadIdx.x;
    const long PER = WK - TT;                    // 126
    const long NW = (long)BHn * TT * PER;
    bf16 zz = __float2bfloat16(0.f);
    if (i < NW) {
        long row = i / PER, j = i - row * PER;
        size_t off = (size_t)row * WK + TT + j;
        g_wph[off] = zz; g_wpl[off] = zz;
    } else {
        i -= NW;
        const long NV = (long)BHn * DD * PER;
        if (i < NV) {
            long row = i / PER, j = i - row * PER;
            size_t off = (size_t)row * WK + TT + j;
            g_vTh[off] = zz; g_vTl[off] = zz;
        }
    }
}

// ---- embed ----
__global__ void init_h_kernel(const float* __restrict__ x,
                              const float* __restrict__ cls,
                              const float* __restrict__ dict) {
    long i = (long)blockIdx.x * blockDim.x + threadIdx.x;
    if (i >= (long)MM * DD) return;
    int d = (int)(i % DD);
    long r = i / DD;
    int t = (int)(r % TT);
    int b = (int)(r / TT);
    float v;
    if (t < NTOK)        v = x[((long)b * NTOK + t) * DD + d];
    else if (t == NTOK)  v = cls[d];
    else                 v = dict[d];
    g_h[i] = v;
}

// ---- layernorm: fp32 in -> bf16 hi/lo out ----
__global__ void ln_kernel(const float* __restrict__ in,
                          bf16* __restrict__ outh, bf16* __restrict__ outl,
                          const float* __restrict__ gamma, const float* __restrict__ beta) {
    int row = blockIdx.x;
    int tid = threadIdx.x;
    float x = in[(long)row * DD + tid];
    float s = x, s2 = x * x;
    #pragma unroll
    for (int o = 16; o > 0; o >>= 1) {
        s  += __shfl_xor_sync(0xFFFFFFFFu, s,  o);
        s2 += __shfl_xor_sync(0xFFFFFFFFu, s2, o);
    }
    __shared__ float sh[8], sh2[8];
    int w = tid >> 5;
    if ((tid & 31) == 0) { sh[w] = s; sh2[w] = s2; }
    __syncthreads();
    if (tid < 32) {
        float a  = (tid < 8) ? sh[tid]  : 0.f;
        float a2 = (tid < 8) ? sh2[tid] : 0.f;
        #pragma unroll
        for (int o = 4; o > 0; o >>= 1) {
            a  += __shfl_xor_sync(0xFFFFFFFFu, a,  o);
            a2 += __shfl_xor_sync(0xFFFFFFFFu, a2, o);
        }
        if (tid == 0) { sh[0] = a; sh2[0] = a2; }
    }
    __syncthreads();
    float mean = sh[0] * (1.0f / DD);
    float var  = sh2[0] * (1.0f / DD) - mean * mean;
    float rr = rsqrtf(var + 1e-5f);
    float y = (x - mean) * rr * gamma[tid] + beta[tid];
    split_store(outh, outl, (size_t)row * DD + tid, y);
}

// ---- softmax: fp32 scores -> bf16 hi/lo probs (stride WK) ----
__global__ void softmax_kernel() {
    long row = blockIdx.x;             // bh*TT + t
    int bh = (int)(row / TT);
    int t  = (int)(row % TT);
    const float* p = g_s + (size_t)bh * TT * TS + (size_t)t * TS;
    size_t wo = ((size_t)bh * TT + t) * WK;
    int tid = threadIdx.x;
    float v[5];
    float mx = -1e30f;
    #pragma unroll
    for (int it = 0; it < 5; it++) {
        int j = tid + it * 256;
        if (j < TT) { v[it] = p[j]; mx = fmaxf(mx, v[it]); }
    }
    __shared__ float red_m[8], red_s[8];
    #pragma unroll
    for (int o = 16; o > 0; o >>= 1) mx = fmaxf(mx, __shfl_xor_sync(0xFFFFFFFFu, mx, o));
    if ((tid & 31) == 0) red_m[tid >> 5] = mx;
    __syncthreads();
    if (tid < 32) {
        float a = (tid < 8) ? red_m[tid] : -1e30f;
        #pragma unroll
        for (int o = 4; o > 0; o >>= 1) a = fmaxf(a, __shfl_xor_sync(0xFFFFFFFFu, a, o));
        if (tid == 0) red_m[0] = a;
    }
    __syncthreads();
    mx = red_m[0];
    float sum = 0.f;
    #pragma unroll
    for (int it = 0; it < 5; it++) {
        int j = tid + it * 256;
        if (j < TT) { v[it] = __expf(v[it] - mx); sum += v[it]; }
    }
    #pragma unroll
    for (int o = 16; o > 0; o >>= 1) sum += __shfl_xor_sync(0xFFFFFFFFu, sum, o);
    if ((tid & 31) == 0) red_s[tid >> 5] = sum;
    __syncthreads();
    if (tid < 32) {
        float a = (tid < 8) ? red_s[tid] : 0.f;
        #pragma unroll
        for (int o = 4; o > 0; o >>= 1) a += __shfl_xor_sync(0xFFFFFFFFu, a, o);
        if (tid == 0) red_s[0] = a;
    }
    __syncthreads();
    float inv = 1.0f / red_s[0];
    #pragma unroll
    for (int it = 0; it < 5; it++) {
        int j = tid + it * 256;
        if (j < TT) split_store(g_wph, g_wpl, wo + j, v[it] * inv);
    }
}

// ---- final output split ----
__global__ void out_kernel(float* __restrict__ out) {
    long i = (long)blockIdx.x * blockDim.x + threadIdx.x;
    if (i >= (long)MM * DD) return;
    int d = (int)(i % DD);
    long r = i / DD;
    int t = (int)(r % TT);
    int b = (int)(r / TT);
    float v = g_h[i];
    if (t < NTOK)        out[((long)b * NTOK + t) * DD + d] = v;
    else if (t == NTOK)  out[(long)BB * NTOK * DD + (long)b * DD + d] = v;
    else                 out[(long)BB * NTOK * DD + (long)BB * DD + (long)b * DD + d] = v;
}

extern "C" void kernel_launch(void* const* d_in, const int* in_sizes, int n_in,
                              void* d_out, int out_size) {
    const float* x      = (const float*)d_in[0];
    const float* cls    = (const float*)d_in[1];
    const float* dict   = (const float*)d_in[2];
    const float* ln1_g  = (const float*)d_in[3];
    const float* ln1_b  = (const float*)d_in[4];
    const float* qkv_w  = (const float*)d_in[5];
    const float* qkv_b  = (const float*)d_in[6];
    const float* proj_w = (const float*)d_in[7];
    const float* proj_b = (const float*)d_in[8];
    const float* ln2_g  = (const float*)d_in[9];
    const float* ln2_b  = (const float*)d_in[10];
    const float* mlp_w1 = (const float*)d_in[11];
    const float* mlp_b1 = (const float*)d_in[12];
    const float* mlp_w2 = (const float*)d_in[13];
    const float* mlp_b2 = (const float*)d_in[14];

    float *gh, *gs;
    bf16 *lnh, *lnl, *qh, *ql, *kh, *kl, *vTh, *vTl, *wph, *wpl, *oh, *ol, *mh, *ml;
    bf16 *qkvTh, *qkvTl, *projTh, *projTl, *w1Th, *w1Tl, *w2Th, *w2Tl;
    cudaGetSymbolAddress((void**)&gh,  g_h);
    cudaGetSymbolAddress((void**)&gs,  g_s);
    cudaGetSymbolAddress((void**)&lnh, g_lnh);
    cudaGetSymbolAddress((void**)&lnl, g_lnl);
    cudaGetSymbolAddress((void**)&qh,  g_qh);
    cudaGetSymbolAddress((void**)&ql,  g_ql);
    cudaGetSymbolAddress((void**)&kh,  g_kh);
    cudaGetSymbolAddress((void**)&kl,  g_kl);
    cudaGetSymbolAddress((void**)&vTh, g_vTh);
    cudaGetSymbolAddress((void**)&vTl, g_vTl);
    cudaGetSymbolAddress((void**)&wph, g_wph);
    cudaGetSymbolAddress((void**)&wpl, g_wpl);
    cudaGetSymbolAddress((void**)&oh,  g_oh);
    cudaGetSymbolAddress((void**)&ol,  g_ol);
    cudaGetSymbolAddress((void**)&mh,  g_mh);
    cudaGetSymbolAddress((void**)&ml,  g_ml);
    cudaGetSymbolAddress((void**)&qkvTh, g_qkvTh);
    cudaGetSymbolAddress((void**)&qkvTl, g_qkvTl);
    cudaGetSymbolAddress((void**)&projTh, g_projTh);
    cudaGetSymbolAddress((void**)&projTl, g_projTl);
    cudaGetSymbolAddress((void**)&w1Th, g_w1Th);
    cudaGetSymbolAddress((void**)&w1Tl, g_w1Tl);
    cudaGetSymbolAddress((void**)&w2Th, g_w2Th);
    cudaGetSymbolAddress((void**)&w2Tl, g_w2Tl);

    // weight prep: transpose + bf16 hi/lo split, per layer
    dim3 tb(32, 8);
    for (int l = 0; l < LL; l++) {
        tsplit<<<dim3(HD3/32, DD/32), tb>>>(qkv_w + (size_t)l*DD*HD3,
                                            qkvTh + (size_t)l*HD3*DD, qkvTl + (size_t)l*HD3*DD, DD, HD3);
        tsplit<<<dim3(DD/32, OD/32), tb>>>(proj_w + (size_t)l*OD*DD,
                                           projTh + (size_t)l*DD*OD, projTl + (size_t)l*DD*OD, OD, DD);
        tsplit<<<dim3(ED/32, DD/32), tb>>>(mlp_w1 + (size_t)l*DD*ED,
                                           w1Th + (size_t)l*ED*DD, w1Tl + (size_t)l*ED*DD, DD, ED);
        tsplit<<<dim3(DD/32, ED/32), tb>>>(mlp_w2 + (size_t)l*ED*DD,
                                           w2Th + (size_t)l*DD*ED, w2Tl + (size_t)l*DD*ED, ED, DD);
    }
    {
        long tot = (long)BHn*TT*(WK-TT) + (long)BHn*DD*(WK-TT);
        zero_pads<<<(unsigned)((tot + 255) / 256), 256>>>();
    }

    long total = (long)MM * DD;
    init_h_kernel<<<(unsigned)((total + 255) / 256), 256>>>(x, cls, dict);

    for (int l = 0; l < LL; l++) {
        ln_kernel<<<MM, 256>>>(gh, lnh, lnl, ln1_g + (size_t)l*DD, ln1_b + (size_t)l*DD);

        // QKV: [8208,256] x [6144,256]^T, scatter epilogue
        mma_gemm<1><<<dim3(HD3/128, (MM+127)/128, 1), 256>>>(
            lnh, lnl, DD, 0,
            qkvTh + (size_t)l*HD3*DD, qkvTl + (size_t)l*HD3*DD, DD, 0,
            qkv_b + (size_t)l*HD3, nullptr, 0, 0, MM, HD3, DD);

        // scores = Q K^T, batched over 64 heads
        mma_gemm<0><<<dim3((TT+127)/128, (TT+127)/128, BHn), 256>>>(
            qh, ql, DD, (long)TT*DD,
            kh, kl, DD, (long)TT*DD,
            nullptr, gs, TS, (long)TT*TS, TT, TT, DD);

        softmax_kernel<<<BHn*TT, 256>>>();

        // O = W V  (A = probs [T,WK], B = vT [256,WK])
        mma_gemm<2><<<dim3(DD/128, (TT+127)/128, BHn), 256>>>(
            wph, wpl, WK, (long)TT*WK,
            vTh, vTl, WK, (long)DD*WK,
            nullptr, nullptr, 0, 0, TT, DD, WK);

        // proj: [8208,2048] x [256,2048]^T -> fp32 h
        mma_gemm<3><<<dim3(DD/128, (MM+127)/128, 1), 256>>>(
            oh, ol, OD, 0,
            projTh + (size_t)l*DD*OD, projTl + (size_t)l*DD*OD, OD, 0,
            proj_b + (size_t)l*DD, gh, DD, 0, MM, DD, OD);

        ln_kernel<<<MM, 256>>>(gh, lnh, lnl, ln2_g + (size_t)l*DD, ln2_b + (size_t)l*DD);

        // mlp1 + gelu -> m split
        mma_gemm<4><<<dim3(ED/128, (MM+127)/128, 1), 256>>>(
            lnh, lnl, DD, 0,
            w1Th + (size_t)l*ED*DD, w1Tl + (size_t)l*ED*DD, DD, 0,
            mlp_b1 + (size_t)l*ED, nullptr, 0, 0, MM, ED, DD);

        // mlp2 + gelu -> fp32 h
        mma_gemm<5><<<dim3(DD/128, (MM+127)/128, 1), 256>>>(
            mh, ml, ED, 0,
            w2Th + (size_t)l*DD*ED, w2Tl + (size_t)l*DD*ED, ED, 0,
            mlp_b2 + (size_t)l*DD, gh, DD, 0, MM, DD, ED);
    }

    out_kernel<<<(unsigned)((total + 255) / 256), 256>>>((float*)d_out);
}

// round 4
// speedup vs baseline: 2.6574x; 1.3148x over previous
#include <cuda_runtime.h>
#include <cuda_bf16.h>
#include <math.h>
#include <stdint.h>

// ---- problem constants ----
#define BB 8
#define NTOK 1024
#define TT 1026            // N + cls + dict
#define DD 256
#define HH 8
#define LL 6
#define HD3 6144           // H*D*3
#define OD 2048            // H*D
#define ED 1024            // EXP*D
#define MM (BB*TT)         // 8208 rows
#define BHn (BB*HH)        // 64
#define TS 1040            // padded fp32 score row stride
#define WK 1152            // padded K (mult of 128) for prob/vT operands

typedef __nv_bfloat16 bf16;

// ---- scratch (device globals; no allocs allowed) ----
__device__ __align__(16) float g_h [(size_t)MM*DD];
__device__ __align__(16) float g_s [(size_t)BHn*TT*TS];
__device__ __align__(16) float g_qkvb[(size_t)LL*HD3];
__device__ __align__(16) bf16 g_lnh[(size_t)MM*DD];
__device__ __align__(16) bf16 g_lnl[(size_t)MM*DD];
__device__ __align__(16) bf16 g_qh[(size_t)BHn*TT*DD];
__device__ __align__(16) bf16 g_ql[(size_t)BHn*TT*DD];
__device__ __align__(16) bf16 g_kh[(size_t)BHn*TT*DD];
__device__ __align__(16) bf16 g_kl[(size_t)BHn*TT*DD];
__device__ __align__(16) bf16 g_vh[(size_t)BHn*TT*DD];
__device__ __align__(16) bf16 g_vl[(size_t)BHn*TT*DD];
__device__ __align__(16) bf16 g_vTh[(size_t)BHn*DD*WK];
__device__ __align__(16) bf16 g_vTl[(size_t)BHn*DD*WK];
__device__ __align__(16) bf16 g_wph[(size_t)BHn*TT*WK];
__device__ __align__(16) bf16 g_wpl[(size_t)BHn*TT*WK];
__device__ __align__(16) bf16 g_oh[(size_t)MM*OD];
__device__ __align__(16) bf16 g_ol[(size_t)MM*OD];
__device__ __align__(16) bf16 g_mh[(size_t)MM*ED];
__device__ __align__(16) bf16 g_ml[(size_t)MM*ED];
// transposed + split weights [N,K] per layer
__device__ __align__(16) bf16 g_qkvTh[(size_t)LL*HD3*DD];
__device__ __align__(16) bf16 g_qkvTl[(size_t)LL*HD3*DD];
__device__ __align__(16) bf16 g_projTh[(size_t)LL*DD*OD];
__device__ __align__(16) bf16 g_projTl[(size_t)LL*DD*OD];
__device__ __align__(16) bf16 g_w1Th[(size_t)LL*ED*DD];
__device__ __align__(16) bf16 g_w1Tl[(size_t)LL*ED*DD];
__device__ __align__(16) bf16 g_w2Th[(size_t)LL*DD*ED];
__device__ __align__(16) bf16 g_w2Tl[(size_t)LL*DD*ED];

__device__ __forceinline__ float gelu_exact(float x) {
    return 0.5f * x * (1.0f + erff(x * 0.70710678118654752440f));
}

__device__ __forceinline__ uint32_t smem_u32(const void* p) {
    uint32_t a;
    asm("{ .reg .u64 t; cvta.to.shared.u64 t, %1; cvt.u32.u64 %0, t; }" : "=r"(a) : "l"(p));
    return a;
}

__device__ __forceinline__ void ldsm4(uint32_t* r, uint32_t addr) {
    asm volatile("ldmatrix.sync.aligned.m8n8.x4.shared.b16 {%0,%1,%2,%3}, [%4];"
                 : "=r"(r[0]), "=r"(r[1]), "=r"(r[2]), "=r"(r[3]) : "r"(addr));
}

__device__ __forceinline__ void mma16816(float* d, const uint32_t* a, const uint32_t* b) {
    asm volatile(
        "mma.sync.aligned.m16n8k16.row.col.f32.bf16.bf16.f32 "
        "{%0,%1,%2,%3}, {%4,%5,%6,%7}, {%8,%9}, {%0,%1,%2,%3};"
        : "+f"(d[0]), "+f"(d[1]), "+f"(d[2]), "+f"(d[3])
        : "r"(a[0]), "r"(a[1]), "r"(a[2]), "r"(a[3]), "r"(b[0]), "r"(b[1]));
}

__device__ __forceinline__ void cpa16(uint32_t dst, const void* src, bool v) {
    int sz = v ? 16 : 0;
    asm volatile("cp.async.cg.shared.global [%0], [%1], 16, %2;"
                 :: "r"(dst), "l"(src), "r"(sz) : "memory");
}
__device__ __forceinline__ void cpa_commit() {
    asm volatile("cp.async.commit_group;" ::: "memory");
}

__device__ __forceinline__ void split_store(bf16* dh, bf16* dl, size_t off, float v) {
    bf16 h = __float2bfloat16(v);
    dh[off] = h;
    dl[off] = __float2bfloat16(v - __bfloat162float(h));
}

// per-element epilogue
template<int EPI>
__device__ __forceinline__ void epi_store(int gm, int gn, float v, int M, int N,
                                          const float* __restrict__ bias,
                                          float* __restrict__ C, int ldc, long sC, int z) {
    if (gm >= M || gn >= N) return;
    if constexpr (EPI == 0) {                 // scores -> fp32
        C[(size_t)z * sC + (size_t)gm * ldc + gn] = v;
    } else if constexpr (EPI == 1) {          // qkv scatter (permuted cols: c*2048+h*256+f)
        v += bias[gn];
        int c = gn >> 11;
        int rem = gn & 2047;
        int h = rem >> 8, f = rem & 255;
        int b = gm / TT, t = gm - b * TT;
        int bh = b * HH + h;
        size_t o = ((size_t)bh * TT + t) * DD + f;
        if (c == 2) {
            split_store(g_vh, g_vl, o, v);
        } else {
            v *= 0.0625f;                     // 1/sqrt(256)
            if (c == 0) split_store(g_qh, g_ql, o, v);
            else        split_store(g_kh, g_kl, o, v);
        }
    } else if constexpr (EPI == 2) {          // WV -> o split
        int b = z >> 3, head = z & 7;
        split_store(g_oh, g_ol, ((size_t)b * TT + gm) * OD + (size_t)head * DD + gn, v);
    } else if constexpr (EPI == 3) {          // proj -> fp32 + bias
        C[(size_t)gm * ldc + gn] = v + bias[gn];
    } else if constexpr (EPI == 4) {          // mlp1: bias+gelu -> m split
        split_store(g_mh, g_ml, (size_t)gm * ED + gn, gelu_exact(v + bias[gn]));
    } else {                                  // mlp2: bias+gelu -> fp32
        C[(size_t)gm * ldc + gn] = gelu_exact(v + bias[gn]);
    }
}

// ============ HMMA bf16x3 GEMM: 128x128 block, BK=32, cp.async 2-stage ============
// A: [M,K] K-major (hi/lo). B: [N,K] K-major (hi/lo). D = A @ B^T.
// Warp grid 4(m) x 2(n); warp tile 32x64; mma.sync m16n8k16.
#define SLD 40            // padded smem row stride in bf16 (80 bytes)
#define STG_BYTES 40960   // 4 tiles x 128 x SLD x 2B
#define AH_OFF 0
#define AL_OFF 10240
#define BH_OFF 20480
#define BL_OFF 30720
#define SMEM_DYN (2*STG_BYTES)

template<int EPI>
__global__ void __launch_bounds__(256, 2) mma_gemm(
    const bf16* __restrict__ Ah, const bf16* __restrict__ Al, int lda, long sA,
    const bf16* __restrict__ Bh, const bf16* __restrict__ Bl, int ldb, long sB,
    const float* __restrict__ bias,
    float* __restrict__ C, int ldc, long sC,
    int M, int N, int K)
{
    extern __shared__ char smdyn[];
    uint32_t sb = smem_u32(smdyn);

    int tid = threadIdx.x, lane = tid & 31, wid = tid >> 5;
    int wm = wid >> 1, wn = wid & 1;
    int z = blockIdx.z;
    Ah += (size_t)z * sA;  Al += (size_t)z * sA;
    Bh += (size_t)z * sB;  Bl += (size_t)z * sB;
    int bm = blockIdx.y * 128, bn = blockIdx.x * 128;

    // global-load coordinates: each thread owns 2 rows x 16 bytes
    int row0 = tid >> 2, row1 = row0 + 64;
    int cvb = (tid & 3) * 16;                 // byte offset within row
    bool aval0 = (bm + row0) < M, aval1 = (bm + row1) < M;
    bool bval0 = (bn + row0) < N, bval1 = (bn + row1) < N;
    const char* pAh0 = (const char*)(Ah + (size_t)(aval0 ? bm + row0 : 0) * lda) + cvb;
    const char* pAh1 = (const char*)(Ah + (size_t)(aval1 ? bm + row1 : 0) * lda) + cvb;
    const char* pAl0 = (const char*)(Al + (size_t)(aval0 ? bm + row0 : 0) * lda) + cvb;
    const char* pAl1 = (const char*)(Al + (size_t)(aval1 ? bm + row1 : 0) * lda) + cvb;
    const char* pBh0 = (const char*)(Bh + (size_t)(bval0 ? bn + row0 : 0) * ldb) + cvb;
    const char* pBh1 = (const char*)(Bh + (size_t)(bval1 ? bn + row1 : 0) * ldb) + cvb;
    const char* pBl0 = (const char*)(Bl + (size_t)(bval0 ? bn + row0 : 0) * ldb) + cvb;
    const char* pBl1 = (const char*)(Bl + (size_t)(bval1 ? bn + row1 : 0) * ldb) + cvb;
    uint32_t st0 = (uint32_t)(row0 * SLD * 2) + (uint32_t)cvb;
    uint32_t st1 = (uint32_t)(row1 * SLD * 2) + (uint32_t)cvb;

    float d[2][8][4];
    #pragma unroll
    for (int i = 0; i < 2; i++)
        #pragma unroll
        for (int j = 0; j < 8; j++)
            #pragma unroll
            for (int q = 0; q < 4; q++) d[i][j][q] = 0.f;

    // ldmatrix lane addressing
    int group = lane >> 3, lrow = lane & 7;
    int a_row = wm * 32 + (group & 1) * 8 + lrow;
    int a_ko  = (group >> 1) * 8;
    int b_row = wn * 64 + (group >> 1) * 8 + lrow;
    int b_ko  = (group & 1) * 8;
    uint32_t aoff = (uint32_t)(a_row * SLD + a_ko) * 2;
    uint32_t boff = (uint32_t)(b_row * SLD + b_ko) * 2;

    auto issue = [&](int c, int stg) {
        uint32_t s0 = sb + (uint32_t)stg * STG_BYTES;
        size_t adv = (size_t)c * 64;          // 32 bf16 = 64 bytes
        cpa16(s0 + AH_OFF + st0, pAh0 + adv, aval0);
        cpa16(s0 + AH_OFF + st1, pAh1 + adv, aval1);
        cpa16(s0 + AL_OFF + st0, pAl0 + adv, aval0);
        cpa16(s0 + AL_OFF + st1, pAl1 + adv, aval1);
        cpa16(s0 + BH_OFF + st0, pBh0 + adv, bval0);
        cpa16(s0 + BH_OFF + st1, pBh1 + adv, bval1);
        cpa16(s0 + BL_OFF + st0, pBl0 + adv, bval0);
        cpa16(s0 + BL_OFF + st1, pBl1 + adv, bval1);
        cpa_commit();
    };

    int nit = K >> 5;
    issue(0, 0);

    for (int c = 0; c < nit; c++) {
        uint32_t cb = sb + (uint32_t)(c & 1) * STG_BYTES;
        if (c + 1 < nit) {
            issue(c + 1, (c + 1) & 1);
            asm volatile("cp.async.wait_group 1;" ::: "memory");
        } else {
            asm volatile("cp.async.wait_group 0;" ::: "memory");
        }
        __syncthreads();

        #pragma unroll
        for (int ks = 0; ks < 32; ks += 16) {
            uint32_t a_hf[2][4], a_lf[2][4];
            #pragma unroll
            for (int mt = 0; mt < 2; mt++) {
                uint32_t o = cb + aoff + (uint32_t)((mt * 16 * SLD + ks) * 2);
                ldsm4(a_hf[mt], o + AH_OFF);
                ldsm4(a_lf[mt], o + AL_OFF);
            }
            #pragma unroll
            for (int np = 0; np < 4; np++) {
                uint32_t b_hf[4], b_lf[4];
                uint32_t o = cb + boff + (uint32_t)((np * 16 * SLD + ks) * 2);
                ldsm4(b_hf, o + BH_OFF);
                ldsm4(b_lf, o + BL_OFF);
                #pragma unroll
                for (int mt = 0; mt < 2; mt++)
                    #pragma unroll
                    for (int hq = 0; hq < 2; hq++) {
                        float* acc = d[mt][np * 2 + hq];
                        mma16816(acc, a_hf[mt], &b_hf[hq * 2]);
                        mma16816(acc, a_lf[mt], &b_hf[hq * 2]);
                        mma16816(acc, a_hf[mt], &b_lf[hq * 2]);
                    }
            }
        }
        __syncthreads();
    }

    // epilogue
    #pragma unroll
    for (int mt = 0; mt < 2; mt++)
        #pragma unroll
        for (int nt = 0; nt < 8; nt++) {
            int r0 = bm + wm * 32 + mt * 16 + (lane >> 2);
            int c0 = bn + wn * 64 + nt * 8 + (lane & 3) * 2;
            float* dd = d[mt][nt];
            epi_store<EPI>(r0,     c0,     dd[0], M, N, bias, C, ldc, sC, z);
            epi_store<EPI>(r0,     c0 + 1, dd[1], M, N, bias, C, ldc, sC, z);
            epi_store<EPI>(r0 + 8, c0,     dd[2], M, N, bias, C, ldc, sC, z);
            epi_store<EPI>(r0 + 8, c0 + 1, dd[3], M, N, bias, C, ldc, sC, z);
        }
}

// ---- transpose + split weights: src [K,N] fp32 -> dh/dl [N,K] bf16 ----
// PERM=1: permute qkv output columns h*768+f*3+c -> c*2048+h*256+f
template<int PERM>
__global__ void tsplit(const float* __restrict__ src, bf16* __restrict__ dh,
                       bf16* __restrict__ dl, int K, int N) {
    __shared__ float t[32][33];
    int n0 = blockIdx.x * 32, k0 = blockIdx.y * 32;
    int tx = threadIdx.x, ty = threadIdx.y;  // 32 x 8
    #pragma unroll
    for (int i = 0; i < 4; i++) {
        int k = k0 + ty + i * 8, n = n0 + tx;
        if (k < K && n < N) t[ty + i * 8][tx] = src[(size_t)k * N + n];
    }
    __syncthreads();
    #pragma unroll
    for (int i = 0; i < 4; i++) {
        int n = n0 + ty + i * 8, k = k0 + tx;
        if (n < N && k < K) {
            float v = t[tx][ty + i * 8];
            int nd = n;
            if (PERM) {
                int h = n / 768, r = n - h * 768;
                int f = r / 3, c = r - f * 3;
                nd = c * 2048 + h * 256 + f;
            }
            split_store(dh, dl, (size_t)nd * K + k, v);
        }
    }
}

// ---- permute qkv bias into c*2048+h*256+f order (all layers) ----
__global__ void permute_bias(const float* __restrict__ qb) {
    int i = blockIdx.x * blockDim.x + threadIdx.x;
    if (i >= LL * HD3) return;
    int l = i / HD3, j = i - l * HD3;
    int h = j / 768, r = j - h * 768;
    int f = r / 3, c = r - f * 3;
    g_qkvb[(size_t)l * HD3 + c * 2048 + h * 256 + f] = qb[i];
}

// ---- transpose V: [bh][t][f] -> vT [bh][f][t(pad WK)] (hi+lo) ----
__global__ void transpose_v() {
    __shared__ bf16 th[32][33], tl[32][33];
    int bh = blockIdx.z;
    int f0 = blockIdx.x * 32, t0 = blockIdx.y * 32;
    int tx = threadIdx.x, ty = threadIdx.y;   // 32 x 8
    const bf16* vh = g_vh + (size_t)bh * TT * DD;
    const bf16* vl = g_vl + (size_t)bh * TT * DD;
    #pragma unroll
    for (int i = 0; i < 4; i++) {
        int t = t0 + ty + i * 8;
        bf16 a = __float2bfloat16(0.f), b = a;
        if (t < TT) {
            a = vh[(size_t)t * DD + f0 + tx];
            b = vl[(size_t)t * DD + f0 + tx];
        }
        th[ty + i * 8][tx] = a;
        tl[ty + i * 8][tx] = b;
    }
    __syncthreads();
    bf16* dH = g_vTh + (size_t)bh * DD * WK;
    bf16* dL = g_vTl + (size_t)bh * DD * WK;
    #pragma unroll
    for (int i = 0; i < 4; i++) {
        int f = f0 + ty + i * 8, t = t0 + tx;
        dH[(size_t)f * WK + t] = th[tx][ty + i * 8];
        dL[(size_t)f * WK + t] = tl[tx][ty + i * 8];
    }
}

// ---- zero the K-pads of prob buffers (cols [TT,WK)) ----
__global__ void zero_pads() {
    long i = (long)blockIdx.x * blockDim.x + threadIdx.x;
    const long PER = WK - TT;                    // 126
    const long NW = (long)BHn * TT * PER;
    bf16 zz = __float2bfloat16(0.f);
    if (i < NW) {
        long row = i / PER, j = i - row * PER;
        size_t off = (size_t)row * WK + TT + j;
        g_wph[off] = zz; g_wpl[off] = zz;
    }
}

// ---- embed ----
__global__ void init_h_kernel(const float* __restrict__ x,
                              const float* __restrict__ cls,
                              const float* __restrict__ dict) {
    long i = (long)blockIdx.x * blockDim.x + threadIdx.x;
    if (i >= (long)MM * DD) return;
    int d = (int)(i % DD);
    long r = i / DD;
    int t = (int)(r % TT);
    int b = (int)(r / TT);
    float v;
    if (t < NTOK)        v = x[((long)b * NTOK + t) * DD + d];
    else if (t == NTOK)  v = cls[d];
    else                 v = dict[d];
    g_h[i] = v;
}

// ---- layernorm: fp32 in -> bf16 hi/lo out ----
__global__ void ln_kernel(const float* __restrict__ in,
                          bf16* __restrict__ outh, bf16* __restrict__ outl,
                          const float* __restrict__ gamma, const float* __restrict__ beta) {
    int row = blockIdx.x;
    int tid = threadIdx.x;
    float x = in[(long)row * DD + tid];
    float s = x, s2 = x * x;
    #pragma unroll
    for (int o = 16; o > 0; o >>= 1) {
        s  += __shfl_xor_sync(0xFFFFFFFFu, s,  o);
        s2 += __shfl_xor_sync(0xFFFFFFFFu, s2, o);
    }
    __shared__ float sh[8], sh2[8];
    int w = tid >> 5;
    if ((tid & 31) == 0) { sh[w] = s; sh2[w] = s2; }
    __syncthreads();
    if (tid < 32) {
        float a  = (tid < 8) ? sh[tid]  : 0.f;
        float a2 = (tid < 8) ? sh2[tid] : 0.f;
        #pragma unroll
        for (int o = 4; o > 0; o >>= 1) {
            a  += __shfl_xor_sync(0xFFFFFFFFu, a,  o);
            a2 += __shfl_xor_sync(0xFFFFFFFFu, a2, o);
        }
        if (tid == 0) { sh[0] = a; sh2[0] = a2; }
    }
    __syncthreads();
    float mean = sh[0] * (1.0f / DD);
    float var  = sh2[0] * (1.0f / DD) - mean * mean;
    float rr = rsqrtf(var + 1e-5f);
    float y = (x - mean) * rr * gamma[tid] + beta[tid];
    split_store(outh, outl, (size_t)row * DD + tid, y);
}

// ---- softmax: fp32 scores -> bf16 hi/lo probs (stride WK) ----
__global__ void softmax_kernel() {
    long row = blockIdx.x;             // bh*TT + t
    int bh = (int)(row / TT);
    int t  = (int)(row % TT);
    const float* p = g_s + (size_t)bh * TT * TS + (size_t)t * TS;
    size_t wo = ((size_t)bh * TT + t) * WK;
    int tid = threadIdx.x;
    float v[5];
    float mx = -1e30f;
    #pragma unroll
    for (int it = 0; it < 5; it++) {
        int j = tid + it * 256;
        if (j < TT) { v[it] = p[j]; mx = fmaxf(mx, v[it]); }
    }
    __shared__ float red_m[8], red_s[8];
    #pragma unroll
    for (int o = 16; o > 0; o >>= 1) mx = fmaxf(mx, __shfl_xor_sync(0xFFFFFFFFu, mx, o));
    if ((tid & 31) == 0) red_m[tid >> 5] = mx;
    __syncthreads();
    if (tid < 32) {
        float a = (tid < 8) ? red_m[tid] : -1e30f;
        #pragma unroll
        for (int o = 4; o > 0; o >>= 1) a = fmaxf(a, __shfl_xor_sync(0xFFFFFFFFu, a, o));
        if (tid == 0) red_m[0] = a;
    }
    __syncthreads();
    mx = red_m[0];
    float sum = 0.f;
    #pragma unroll
    for (int it = 0; it < 5; it++) {
        int j = tid + it * 256;
        if (j < TT) { v[it] = __expf(v[it] - mx); sum += v[it]; }
    }
    #pragma unroll
    for (int o = 16; o > 0; o >>= 1) sum += __shfl_xor_sync(0xFFFFFFFFu, sum, o);
    if ((tid & 31) == 0) red_s[tid >> 5] = sum;
    __syncthreads();
    if (tid < 32) {
        float a = (tid < 8) ? red_s[tid] : 0.f;
        #pragma unroll
        for (int o = 4; o > 0; o >>= 1) a += __shfl_xor_sync(0xFFFFFFFFu, a, o);
        if (tid == 0) red_s[0] = a;
    }
    __syncthreads();
    float inv = 1.0f / red_s[0];
    #pragma unroll
    for (int it = 0; it < 5; it++) {
        int j = tid + it * 256;
        if (j < TT) split_store(g_wph, g_wpl, wo + j, v[it] * inv);
    }
}

// ---- final output split ----
__global__ void out_kernel(float* __restrict__ out) {
    long i = (long)blockIdx.x * blockDim.x + threadIdx.x;
    if (i >= (long)MM * DD) return;
    int d = (int)(i % DD);
    long r = i / DD;
    int t = (int)(r % TT);
    int b = (int)(r / TT);
    float v = g_h[i];
    if (t < NTOK)        out[((long)b * NTOK + t) * DD + d] = v;
    else if (t == NTOK)  out[(long)BB * NTOK * DD + (long)b * DD + d] = v;
    else                 out[(long)BB * NTOK * DD + (long)BB * DD + (long)b * DD + d] = v;
}

extern "C" void kernel_launch(void* const* d_in, const int* in_sizes, int n_in,
                              void* d_out, int out_size) {
    const float* x      = (const float*)d_in[0];
    const float* cls    = (const float*)d_in[1];
    const float* dict   = (const float*)d_in[2];
    const float* ln1_g  = (const float*)d_in[3];
    const float* ln1_b  = (const float*)d_in[4];
    const float* qkv_w  = (const float*)d_in[5];
    const float* qkv_b  = (const float*)d_in[6];
    const float* proj_w = (const float*)d_in[7];
    const float* proj_b = (const float*)d_in[8];
    const float* ln2_g  = (const float*)d_in[9];
    const float* ln2_b  = (const float*)d_in[10];
    const float* mlp_w1 = (const float*)d_in[11];
    const float* mlp_b1 = (const float*)d_in[12];
    const float* mlp_w2 = (const float*)d_in[13];
    const float* mlp_b2 = (const float*)d_in[14];

    cudaFuncSetAttribute(mma_gemm<0>, cudaFuncAttributeMaxDynamicSharedMemorySize, SMEM_DYN);
    cudaFuncSetAttribute(mma_gemm<1>, cudaFuncAttributeMaxDynamicSharedMemorySize, SMEM_DYN);
    cudaFuncSetAttribute(mma_gemm<2>, cudaFuncAttributeMaxDynamicSharedMemorySize, SMEM_DYN);
    cudaFuncSetAttribute(mma_gemm<3>, cudaFuncAttributeMaxDynamicSharedMemorySize, SMEM_DYN);
    cudaFuncSetAttribute(mma_gemm<4>, cudaFuncAttributeMaxDynamicSharedMemorySize, SMEM_DYN);
    cudaFuncSetAttribute(mma_gemm<5>, cudaFuncAttributeMaxDynamicSharedMemorySize, SMEM_DYN);

    float *gh, *gs, *qkvb;
    bf16 *lnh, *lnl, *qh, *ql, *kh, *kl, *vTh, *vTl, *wph, *wpl, *oh, *ol, *mh, *ml;
    bf16 *qkvTh, *qkvTl, *projTh, *projTl, *w1Th, *w1Tl, *w2Th, *w2Tl;
    cudaGetSymbolAddress((void**)&gh,  g_h);
    cudaGetSymbolAddress((void**)&gs,  g_s);
    cudaGetSymbolAddress((void**)&qkvb, g_qkvb);
    cudaGetSymbolAddress((void**)&lnh, g_lnh);
    cudaGetSymbolAddress((void**)&lnl, g_lnl);
    cudaGetSymbolAddress((void**)&qh,  g_qh);
    cudaGetSymbolAddress((void**)&ql,  g_ql);
    cudaGetSymbolAddress((void**)&kh,  g_kh);
    cudaGetSymbolAddress((void**)&kl,  g_kl);
    cudaGetSymbolAddress((void**)&vTh, g_vTh);
    cudaGetSymbolAddress((void**)&vTl, g_vTl);
    cudaGetSymbolAddress((void**)&wph, g_wph);
    cudaGetSymbolAddress((void**)&wpl, g_wpl);
    cudaGetSymbolAddress((void**)&oh,  g_oh);
    cudaGetSymbolAddress((void**)&ol,  g_ol);
    cudaGetSymbolAddress((void**)&mh,  g_mh);
    cudaGetSymbolAddress((void**)&ml,  g_ml);
    cudaGetSymbolAddress((void**)&qkvTh, g_qkvTh);
    cudaGetSymbolAddress((void**)&qkvTl, g_qkvTl);
    cudaGetSymbolAddress((void**)&projTh, g_projTh);
    cudaGetSymbolAddress((void**)&projTl, g_projTl);
    cudaGetSymbolAddress((void**)&w1Th, g_w1Th);
    cudaGetSymbolAddress((void**)&w1Tl, g_w1Tl);
    cudaGetSymbolAddress((void**)&w2Th, g_w2Th);
    cudaGetSymbolAddress((void**)&w2Tl, g_w2Tl);

    // weight prep: transpose + bf16 hi/lo split (+ qkv column permutation)
    dim3 tb(32, 8);
    for (int l = 0; l < LL; l++) {
        tsplit<1><<<dim3(HD3/32, DD/32), tb>>>(qkv_w + (size_t)l*DD*HD3,
                                               qkvTh + (size_t)l*HD3*DD, qkvTl + (size_t)l*HD3*DD, DD, HD3);
        tsplit<0><<<dim3(DD/32, OD/32), tb>>>(proj_w + (size_t)l*OD*DD,
                                              projTh + (size_t)l*DD*OD, projTl + (size_t)l*DD*OD, OD, DD);
        tsplit<0><<<dim3(ED/32, DD/32), tb>>>(mlp_w1 + (size_t)l*DD*ED,
                                              w1Th + (size_t)l*ED*DD, w1Tl + (size_t)l*ED*DD, DD, ED);
        tsplit<0><<<dim3(DD/32, ED/32), tb>>>(mlp_w2 + (size_t)l*ED*DD,
                                              w2Th + (size_t)l*DD*ED, w2Tl + (size_t)l*DD*ED, ED, DD);
    }
    permute_bias<<<(LL*HD3 + 255)/256, 256>>>(qkv_b);
    {
        long tot = (long)BHn*TT*(WK-TT);
        zero_pads<<<(unsigned)((tot + 255) / 256), 256>>>();
    }

    long total = (long)MM * DD;
    init_h_kernel<<<(unsigned)((total + 255) / 256), 256>>>(x, cls, dict);

    for (int l = 0; l < LL; l++) {
        ln_kernel<<<MM, 256>>>(gh, lnh, lnl, ln1_g + (size_t)l*DD, ln1_b + (size_t)l*DD);

        // QKV: [8208,256] x [6144,256]^T, permuted scatter epilogue
        mma_gemm<1><<<dim3(HD3/128, (MM+127)/128, 1), 256, SMEM_DYN>>>(
            lnh, lnl, DD, 0,
            qkvTh + (size_t)l*HD3*DD, qkvTl + (size_t)l*HD3*DD, DD, 0,
            qkvb + (size_t)l*HD3, nullptr, 0, 0, MM, HD3, DD);

        // V transpose into [bh][f][t] (zero-padded K)
        transpose_v<<<dim3(DD/32, WK/32, BHn), tb>>>();

        // scores = Q K^T, batched over 64 heads
        mma_gemm<0><<<dim3((TT+127)/128, (TT+127)/128, BHn), 256, SMEM_DYN>>>(
            qh, ql, DD, (long)TT*DD,
            kh, kl, DD, (long)TT*DD,
            nullptr, gs, TS, (long)TT*TS, TT, TT, DD);

        softmax_kernel<<<BHn*TT, 256>>>();

        // O = W V  (A = probs [T,WK], B = vT [256,WK])
        mma_gemm<2><<<dim3(DD/128, (TT+127)/128, BHn), 256, SMEM_DYN>>>(
            wph, wpl, WK, (long)TT*WK,
            vTh, vTl, WK, (long)DD*WK,
            nullptr, nullptr, 0, 0, TT, DD, WK);

        // proj: [8208,2048] x [256,2048]^T -> fp32 h
        mma_gemm<3><<<dim3(DD/128, (MM+127)/128, 1), 256, SMEM_DYN>>>(
            oh, ol, OD, 0,
            projTh + (size_t)l*DD*OD, projTl + (size_t)l*DD*OD, OD, 0,
            proj_b + (size_t)l*DD, gh, DD, 0, MM, DD, OD);

        ln_kernel<<<MM, 256>>>(gh, lnh, lnl, ln2_g + (size_t)l*DD, ln2_b + (size_t)l*DD);

        // mlp1 + gelu -> m split
        mma_gemm<4><<<dim3(ED/128, (MM+127)/128, 1), 256, SMEM_DYN>>>(
            lnh, lnl, DD, 0,
            w1Th + (size_t)l*ED*DD, w1Tl + (size_t)l*ED*DD, DD, 0,
            mlp_b1 + (size_t)l*ED, nullptr, 0, 0, MM, ED, DD);

        // mlp2 + gelu -> fp32 h
        mma_gemm<5><<<dim3(DD/128, (MM+127)/128, 1), 256, SMEM_DYN>>>(
            mh, ml, ED, 0,
            w2Th + (size_t)l*DD*ED, w2Tl + (size_t)l*DD*ED, ED, 0,
            mlp_b2 + (size_t)l*DD, gh, DD, 0, MM, DD, ED);
    }

    out_kernel<<<(unsigned)((total + 255) / 256), 256>>>((float*)d_out);
}